// round 6
// baseline (speedup 1.0000x reference)
#include <cuda_runtime.h>
#include <cuda_bf16.h>
#include <math.h>
#include <stdint.h>

// ---------------------------------------------------------------------------
// AutomaticBrightnessAndContrast  —  in/out f32 [3, H, W]
// K1 fused max + hist(scale=255)   (one full read, 256-bit loads)
// K2 conditional hist(scale=1)     (early-exits when max<=1)
// K3 parallel scan -> params; resets scratch for next graph replay
// K4 pointwise affine+clamp        (256-bit streaming ld/st, 16 floats/thread)
// ---------------------------------------------------------------------------

#define NUM_BINS 256
#define HIST_BLOCKS 1024
#define HIST_THREADS 256
#define WARPS_PER_BLOCK (HIST_THREADS / 32)

__device__ unsigned g_hist255[NUM_BINS];   // zero-init at module load
__device__ unsigned g_hist1[NUM_BINS];     // zero-init at module load
__device__ unsigned g_maxbits;             // zero-init (= most-negative key)
__device__ float    g_alpha_eff;
__device__ float    g_beta_eff;
__device__ float    g_hi;
__device__ int      g_identity;

__device__ __forceinline__ unsigned fkey(float f) {
    unsigned b = __float_as_uint(f);
    return (b & 0x80000000u) ? ~b : (b | 0x80000000u);
}
__device__ __forceinline__ float fkey_decode(unsigned k) {
    unsigned b = (k & 0x80000000u) ? (k & 0x7FFFFFFFu) : ~k;
    return __uint_as_float(b);
}

// ---- 256-bit global memory ops (sm_100a) ----------------------------------
__device__ __forceinline__ void ldg256(const float4* p, float4& a, float4& b) {
    asm volatile("ld.global.v8.f32 {%0,%1,%2,%3,%4,%5,%6,%7}, [%8];"
        : "=f"(a.x), "=f"(a.y), "=f"(a.z), "=f"(a.w),
          "=f"(b.x), "=f"(b.y), "=f"(b.z), "=f"(b.w)
        : "l"(p));
}
__device__ __forceinline__ void ldg256_cs(const float4* p, float4& a, float4& b) {
    asm volatile("ld.global.cs.v8.f32 {%0,%1,%2,%3,%4,%5,%6,%7}, [%8];"
        : "=f"(a.x), "=f"(a.y), "=f"(a.z), "=f"(a.w),
          "=f"(b.x), "=f"(b.y), "=f"(b.z), "=f"(b.w)
        : "l"(p));
}
__device__ __forceinline__ void stg256_cs(float4* p, const float4& a, const float4& b) {
    asm volatile("st.global.cs.v8.f32 [%0], {%1,%2,%3,%4,%5,%6,%7,%8};"
        :: "l"(p),
           "f"(a.x), "f"(a.y), "f"(a.z), "f"(a.w),
           "f"(b.x), "f"(b.y), "f"(b.z), "f"(b.w)
        : "memory");
}

// scaled-bin coefficients: 255 * c * (256/255) = 256 * c
#define CR255 (0.299f * 256.0f)
#define CG255 (0.587f * 256.0f)
#define CB255 (0.114f * 256.0f)
// scale=1 path: c * (256/255)
#define CR1 (0.299f * 256.0f / 255.0f)
#define CG1 (0.587f * 256.0f / 255.0f)
#define CB1 (0.114f * 256.0f / 255.0f)

__device__ __forceinline__ void hist_px255(unsigned* h, float r, float g, float b) {
    // scaled = gray255 * 256/255; valid gray in [0,255] <=> scaled in [0,256]
    float s = fmaf(r, CR255, fmaf(g, CG255, b * CB255));
    if (s >= 0.0f && s <= 256.0f) {
        int idx = min((int)s, NUM_BINS - 1);   // s>=0 -> trunc == floor
        atomicAdd(&h[idx], 1u);
    }
}
__device__ __forceinline__ void hist_px1(unsigned* h, float r, float g, float b) {
    float s = fmaf(r, CR1, fmaf(g, CG1, b * CB1));
    if (s >= 0.0f && s <= 256.0f) {
        int idx = min((int)s, NUM_BINS - 1);
        atomicAdd(&h[idx], 1u);
    }
}

__device__ __forceinline__ float max8(const float4& a, const float4& b) {
    return fmaxf(fmaxf(fmaxf(a.x, a.y), fmaxf(a.z, a.w)),
                 fmaxf(fmaxf(b.x, b.y), fmaxf(b.z, b.w)));
}

// ------------------------------- K1 ----------------------------------------
// pair-indexed: p counts 32B chunks (8 floats) within one plane
__global__ __launch_bounds__(HIST_THREADS)
void hist255_max_kernel(const float4* __restrict__ img, int n4per, int n8per) {
    __shared__ unsigned sh[WARPS_PER_BLOCK][NUM_BINS];
    __shared__ float    smax[WARPS_PER_BLOCK];

    const int tid  = threadIdx.x;
    const int wid  = tid >> 5;
    const int lane = tid & 31;

    for (int i = tid; i < WARPS_PER_BLOCK * NUM_BINS; i += blockDim.x)
        (&sh[0][0])[i] = 0u;
    __syncthreads();

    unsigned* myh = sh[wid];
    float lmax = -INFINITY;

    const int stride = gridDim.x * blockDim.x;
    for (int p = blockIdx.x * blockDim.x + tid; p < n8per; p += stride) {
        float4 r0, r1, g0, g1, b0, b1;
        ldg256(&img[2 * p],              r0, r1);
        ldg256(&img[2 * p + n4per],      g0, g1);
        ldg256(&img[2 * p + 2 * n4per],  b0, b1);

        lmax = fmaxf(lmax, fmaxf(max8(r0, r1), fmaxf(max8(g0, g1), max8(b0, b1))));

        hist_px255(myh, r0.x, g0.x, b0.x);
        hist_px255(myh, r0.y, g0.y, b0.y);
        hist_px255(myh, r0.z, g0.z, b0.z);
        hist_px255(myh, r0.w, g0.w, b0.w);
        hist_px255(myh, r1.x, g1.x, b1.x);
        hist_px255(myh, r1.y, g1.y, b1.y);
        hist_px255(myh, r1.z, g1.z, b1.z);
        hist_px255(myh, r1.w, g1.w, b1.w);
    }

    // odd-tail float4 (only if n4per is odd; not hit for 4096x4096)
    if (blockIdx.x == 0 && tid == 0 && (2 * n8per) < n4per) {
        int t = 2 * n8per;
        float4 r4 = img[t], g4 = img[t + n4per], b4 = img[t + 2 * n4per];
        lmax = fmaxf(lmax, fmaxf(fmaxf(fmaxf(r4.x, r4.y), fmaxf(r4.z, r4.w)),
                       fmaxf(fmaxf(fmaxf(g4.x, g4.y), fmaxf(g4.z, g4.w)),
                             fmaxf(fmaxf(b4.x, b4.y), fmaxf(b4.z, b4.w)))));
        hist_px255(myh, r4.x, g4.x, b4.x);
        hist_px255(myh, r4.y, g4.y, b4.y);
        hist_px255(myh, r4.z, g4.z, b4.z);
        hist_px255(myh, r4.w, g4.w, b4.w);
    }
    __syncthreads();

    for (int b = tid; b < NUM_BINS; b += blockDim.x) {
        unsigned s = 0;
        #pragma unroll
        for (int w = 0; w < WARPS_PER_BLOCK; w++) s += sh[w][b];
        if (s) atomicAdd(&g_hist255[b], s);
    }

    #pragma unroll
    for (int off = 16; off; off >>= 1)
        lmax = fmaxf(lmax, __shfl_xor_sync(0xFFFFFFFFu, lmax, off));
    if (lane == 0) smax[wid] = lmax;
    __syncthreads();
    if (tid == 0) {
        float m = smax[0];
        #pragma unroll
        for (int w = 1; w < WARPS_PER_BLOCK; w++) m = fmaxf(m, smax[w]);
        atomicMax(&g_maxbits, fkey(m));
    }
}

// ------------------------------- K2 ----------------------------------------
__global__ __launch_bounds__(HIST_THREADS)
void hist1_kernel(const float4* __restrict__ img, int n4per) {
    if (fkey_decode(g_maxbits) <= 1.0f) return;

    __shared__ unsigned sh[WARPS_PER_BLOCK][NUM_BINS];
    const int tid = threadIdx.x;
    const int wid = tid >> 5;

    for (int i = tid; i < WARPS_PER_BLOCK * NUM_BINS; i += blockDim.x)
        (&sh[0][0])[i] = 0u;
    __syncthreads();

    unsigned* myh = sh[wid];
    const int stride = gridDim.x * blockDim.x;
    for (int i = blockIdx.x * blockDim.x + tid; i < n4per; i += stride) {
        float4 r4 = img[i];
        float4 g4 = img[i + n4per];
        float4 b4 = img[i + 2 * n4per];
        hist_px1(myh, r4.x, g4.x, b4.x);
        hist_px1(myh, r4.y, g4.y, b4.y);
        hist_px1(myh, r4.z, g4.z, b4.z);
        hist_px1(myh, r4.w, g4.w, b4.w);
    }
    __syncthreads();

    for (int b = tid; b < NUM_BINS; b += blockDim.x) {
        unsigned s = 0;
        #pragma unroll
        for (int w = 0; w < WARPS_PER_BLOCK; w++) s += sh[w][b];
        if (s) atomicAdd(&g_hist1[b], s);
    }
}

// ------------------------------- K3 ----------------------------------------
__global__ __launch_bounds__(NUM_BINS)
void params_kernel() {
    __shared__ float acc[NUM_BINS];
    const int tid = threadIdx.x;

    float maxv = fkey_decode(g_maxbits);
    bool  is_norm = (maxv <= 1.0f);
    float scale = is_norm ? 255.0f : 1.0f;

    float v = (float)(is_norm ? g_hist255[tid] : g_hist1[tid]);

    acc[tid] = v;
    __syncthreads();
    #pragma unroll
    for (int off = 1; off < NUM_BINS; off <<= 1) {
        float add = (tid >= off) ? acc[tid - off] : 0.0f;
        __syncthreads();
        acc[tid] += add;
        __syncthreads();
    }

    float maximum = acc[NUM_BINS - 1];
    float clip = (maximum / 100.0f) / 2.0f;          // CLIP_HIST_PERCENT = 1.0
    float upper = maximum - clip;

    int min_gray = __syncthreads_count(acc[tid] < clip);
    int max_gray = __syncthreads_count(acc[tid] < upper) - 1;

    if (tid == 0) {
        float span  = fmaxf((float)(max_gray - min_gray), 1.0f);
        float alpha = 255.0f / span;
        float beta  = -(float)min_gray * alpha;
        g_alpha_eff = alpha / scale;
        g_beta_eff  = beta  / scale;
        g_hi        = is_norm ? 1.0f : 255.0f;
        g_identity  = (max_gray > min_gray) ? 0 : 1;
        g_maxbits   = 0u;
    }
    g_hist255[tid] = 0u;
    g_hist1[tid]   = 0u;
}

// ------------------------------- K4 ----------------------------------------
// 2 x 256-bit loads + 2 x 256-bit stores per thread (16 floats), streaming.
__global__ __launch_bounds__(256)
void apply_kernel(const float4* __restrict__ in, float4* __restrict__ out,
                  int n8, int n4) {
    int c0 = blockIdx.x * 512 + threadIdx.x;   // 32B-chunk indices
    int c1 = c0 + 256;

    float4 a0, a1, b0, b1;
    bool ok0 = c0 < n8, ok1 = c1 < n8;
    if (ok0) ldg256_cs(&in[2 * c0], a0, a1);
    if (ok1) ldg256_cs(&in[2 * c1], b0, b1);

    int   ident = g_identity;
    float a  = g_alpha_eff;
    float b  = g_beta_eff;
    float hi = g_hi;

    if (!ident) {
        a0.x = fminf(fmaxf(fmaf(a0.x, a, b), 0.0f), hi);
        a0.y = fminf(fmaxf(fmaf(a0.y, a, b), 0.0f), hi);
        a0.z = fminf(fmaxf(fmaf(a0.z, a, b), 0.0f), hi);
        a0.w = fminf(fmaxf(fmaf(a0.w, a, b), 0.0f), hi);
        a1.x = fminf(fmaxf(fmaf(a1.x, a, b), 0.0f), hi);
        a1.y = fminf(fmaxf(fmaf(a1.y, a, b), 0.0f), hi);
        a1.z = fminf(fmaxf(fmaf(a1.z, a, b), 0.0f), hi);
        a1.w = fminf(fmaxf(fmaf(a1.w, a, b), 0.0f), hi);
        b0.x = fminf(fmaxf(fmaf(b0.x, a, b), 0.0f), hi);
        b0.y = fminf(fmaxf(fmaf(b0.y, a, b), 0.0f), hi);
        b0.z = fminf(fmaxf(fmaf(b0.z, a, b), 0.0f), hi);
        b0.w = fminf(fmaxf(fmaf(b0.w, a, b), 0.0f), hi);
        b1.x = fminf(fmaxf(fmaf(b1.x, a, b), 0.0f), hi);
        b1.y = fminf(fmaxf(fmaf(b1.y, a, b), 0.0f), hi);
        b1.z = fminf(fmaxf(fmaf(b1.z, a, b), 0.0f), hi);
        b1.w = fminf(fmaxf(fmaf(b1.w, a, b), 0.0f), hi);
    }
    if (ok0) stg256_cs(&out[2 * c0], a0, a1);
    if (ok1) stg256_cs(&out[2 * c1], b0, b1);

    // odd-tail float4 (only if n4 odd; not hit for this shape)
    if (blockIdx.x == 0 && threadIdx.x == 0 && (2 * n8) < n4) {
        int t = 2 * n8;
        float4 v = in[t];
        if (!ident) {
            v.x = fminf(fmaxf(fmaf(v.x, a, b), 0.0f), hi);
            v.y = fminf(fmaxf(fmaf(v.y, a, b), 0.0f), hi);
            v.z = fminf(fmaxf(fmaf(v.z, a, b), 0.0f), hi);
            v.w = fminf(fmaxf(fmaf(v.w, a, b), 0.0f), hi);
        }
        out[t] = v;
    }
}

// ---------------------------------------------------------------------------
extern "C" void kernel_launch(void* const* d_in, const int* in_sizes, int n_in,
                              void* d_out, int out_size) {
    const float* img = (const float*)d_in[0];
    int n_total = in_sizes[0];
    int n_per   = n_total / 3;
    int n4per   = n_per / 4;
    int n8per   = n_per / 8;
    int n4      = n_total / 4;
    int n8      = n_total / 8;

    hist255_max_kernel<<<HIST_BLOCKS, HIST_THREADS>>>((const float4*)img, n4per, n8per);
    hist1_kernel<<<HIST_BLOCKS, HIST_THREADS>>>((const float4*)img, n4per);
    params_kernel<<<1, NUM_BINS>>>();
    int apply_blocks = (n8 + 511) / 512;
    apply_kernel<<<apply_blocks, 256>>>((const float4*)img, (float4*)d_out, n8, n4);
}

// round 8
// speedup vs baseline: 1.0116x; 1.0116x over previous
#include <cuda_runtime.h>
#include <cuda_bf16.h>
#include <math.h>
#include <stdint.h>

// ---------------------------------------------------------------------------
// AutomaticBrightnessAndContrast  —  in/out f32 [3, H, W]
// K1 fused max + hist(scale=255)   (float4 batch-of-2 loads, folded bin coeffs)
// K2 conditional hist(scale=1)     (early-exits when max<=1)
// K3 parallel scan -> params; resets scratch for next graph replay
// K4 pointwise affine+clamp        (256-bit streaming ld/st, 16 floats/thread)
// ---------------------------------------------------------------------------

#define NUM_BINS 256
#define HIST_BLOCKS 1024
#define HIST_THREADS 256
#define WARPS_PER_BLOCK (HIST_THREADS / 32)

__device__ unsigned g_hist255[NUM_BINS];   // zero-init at module load
__device__ unsigned g_hist1[NUM_BINS];     // zero-init at module load
__device__ unsigned g_maxbits;             // zero-init (= most-negative key)
__device__ float    g_alpha_eff;
__device__ float    g_beta_eff;
__device__ float    g_hi;
__device__ int      g_identity;

__device__ __forceinline__ unsigned fkey(float f) {
    unsigned b = __float_as_uint(f);
    return (b & 0x80000000u) ? ~b : (b | 0x80000000u);
}
__device__ __forceinline__ float fkey_decode(unsigned k) {
    unsigned b = (k & 0x80000000u) ? (k & 0x7FFFFFFFu) : ~k;
    return __uint_as_float(b);
}

// ---- 256-bit global memory ops (sm_100a) ----------------------------------
__device__ __forceinline__ void ldg256_cs(const float4* p, float4& a, float4& b) {
    asm volatile("ld.global.cs.v8.f32 {%0,%1,%2,%3,%4,%5,%6,%7}, [%8];"
        : "=f"(a.x), "=f"(a.y), "=f"(a.z), "=f"(a.w),
          "=f"(b.x), "=f"(b.y), "=f"(b.z), "=f"(b.w)
        : "l"(p));
}
__device__ __forceinline__ void stg256_cs(float4* p, const float4& a, const float4& b) {
    asm volatile("st.global.cs.v8.f32 [%0], {%1,%2,%3,%4,%5,%6,%7,%8};"
        :: "l"(p),
           "f"(a.x), "f"(a.y), "f"(a.z), "f"(a.w),
           "f"(b.x), "f"(b.y), "f"(b.z), "f"(b.w)
        : "memory");
}

// scaled-bin coefficients: 255 * c * (256/255) = 256 * c
#define CR255 (0.299f * 256.0f)
#define CG255 (0.587f * 256.0f)
#define CB255 (0.114f * 256.0f)
// scale=1 path: c * (256/255)
#define CR1 (0.299f * 256.0f / 255.0f)
#define CG1 (0.587f * 256.0f / 255.0f)
#define CB1 (0.114f * 256.0f / 255.0f)

__device__ __forceinline__ void hist_px255(unsigned* h, float r, float g, float b) {
    // scaled = gray255 * 256/255; valid gray in [0,255] <=> scaled in [0,256]
    float s = fmaf(r, CR255, fmaf(g, CG255, b * CB255));
    if (s >= 0.0f && s <= 256.0f) {
        int idx = min((int)s, NUM_BINS - 1);   // s>=0 -> trunc == floor
        atomicAdd(&h[idx], 1u);
    }
}
__device__ __forceinline__ void hist_px1(unsigned* h, float r, float g, float b) {
    float s = fmaf(r, CR1, fmaf(g, CG1, b * CB1));
    if (s >= 0.0f && s <= 256.0f) {
        int idx = min((int)s, NUM_BINS - 1);
        atomicAdd(&h[idx], 1u);
    }
}

// ------------------------------- K1 ----------------------------------------
__global__ __launch_bounds__(HIST_THREADS)
void hist255_max_kernel(const float4* __restrict__ img, int n4per) {
    __shared__ unsigned sh[WARPS_PER_BLOCK][NUM_BINS];
    __shared__ float    smax[WARPS_PER_BLOCK];

    const int tid  = threadIdx.x;
    const int wid  = tid >> 5;
    const int lane = tid & 31;

    for (int i = tid; i < WARPS_PER_BLOCK * NUM_BINS; i += blockDim.x)
        (&sh[0][0])[i] = 0u;
    __syncthreads();

    unsigned* myh = sh[wid];
    float lmax = -INFINITY;

    const int stride  = gridDim.x * blockDim.x;
    const int stride2 = 2 * stride;
    int i = blockIdx.x * blockDim.x + tid;

    for (; i + stride < n4per; i += stride2) {
        // batch of 2: issue all 6 128-bit loads up front (MLP=6)
        float4 r4a = img[i];
        float4 g4a = img[i + n4per];
        float4 b4a = img[i + 2 * n4per];
        float4 r4b = img[i + stride];
        float4 g4b = img[i + stride + n4per];
        float4 b4b = img[i + stride + 2 * n4per];

        lmax = fmaxf(lmax, fmaxf(fmaxf(fmaxf(r4a.x, r4a.y), fmaxf(r4a.z, r4a.w)),
                       fmaxf(fmaxf(fmaxf(g4a.x, g4a.y), fmaxf(g4a.z, g4a.w)),
                             fmaxf(fmaxf(fmaxf(b4a.x, b4a.y), fmaxf(b4a.z, b4a.w)),
                       fmaxf(fmaxf(fmaxf(r4b.x, r4b.y), fmaxf(r4b.z, r4b.w)),
                       fmaxf(fmaxf(fmaxf(g4b.x, g4b.y), fmaxf(g4b.z, g4b.w)),
                             fmaxf(fmaxf(b4b.x, b4b.y), fmaxf(b4b.z, b4b.w))))))));

        hist_px255(myh, r4a.x, g4a.x, b4a.x);
        hist_px255(myh, r4a.y, g4a.y, b4a.y);
        hist_px255(myh, r4a.z, g4a.z, b4a.z);
        hist_px255(myh, r4a.w, g4a.w, b4a.w);
        hist_px255(myh, r4b.x, g4b.x, b4b.x);
        hist_px255(myh, r4b.y, g4b.y, b4b.y);
        hist_px255(myh, r4b.z, g4b.z, b4b.z);
        hist_px255(myh, r4b.w, g4b.w, b4b.w);
    }
    for (; i < n4per; i += stride) {
        float4 r4 = img[i];
        float4 g4 = img[i + n4per];
        float4 b4 = img[i + 2 * n4per];
        lmax = fmaxf(lmax, fmaxf(fmaxf(fmaxf(r4.x, r4.y), fmaxf(r4.z, r4.w)),
                       fmaxf(fmaxf(fmaxf(g4.x, g4.y), fmaxf(g4.z, g4.w)),
                             fmaxf(fmaxf(b4.x, b4.y), fmaxf(b4.z, b4.w)))));
        hist_px255(myh, r4.x, g4.x, b4.x);
        hist_px255(myh, r4.y, g4.y, b4.y);
        hist_px255(myh, r4.z, g4.z, b4.z);
        hist_px255(myh, r4.w, g4.w, b4.w);
    }
    __syncthreads();

    for (int b = tid; b < NUM_BINS; b += blockDim.x) {
        unsigned s = 0;
        #pragma unroll
        for (int w = 0; w < WARPS_PER_BLOCK; w++) s += sh[w][b];
        if (s) atomicAdd(&g_hist255[b], s);
    }

    #pragma unroll
    for (int off = 16; off; off >>= 1)
        lmax = fmaxf(lmax, __shfl_xor_sync(0xFFFFFFFFu, lmax, off));
    if (lane == 0) smax[wid] = lmax;
    __syncthreads();
    if (tid == 0) {
        float m = smax[0];
        #pragma unroll
        for (int w = 1; w < WARPS_PER_BLOCK; w++) m = fmaxf(m, smax[w]);
        atomicMax(&g_maxbits, fkey(m));
    }
}

// ------------------------------- K2 ----------------------------------------
__global__ __launch_bounds__(HIST_THREADS)
void hist1_kernel(const float4* __restrict__ img, int n4per) {
    if (fkey_decode(g_maxbits) <= 1.0f) return;

    __shared__ unsigned sh[WARPS_PER_BLOCK][NUM_BINS];
    const int tid = threadIdx.x;
    const int wid = tid >> 5;

    for (int i = tid; i < WARPS_PER_BLOCK * NUM_BINS; i += blockDim.x)
        (&sh[0][0])[i] = 0u;
    __syncthreads();

    unsigned* myh = sh[wid];
    const int stride = gridDim.x * blockDim.x;
    for (int i = blockIdx.x * blockDim.x + tid; i < n4per; i += stride) {
        float4 r4 = img[i];
        float4 g4 = img[i + n4per];
        float4 b4 = img[i + 2 * n4per];
        hist_px1(myh, r4.x, g4.x, b4.x);
        hist_px1(myh, r4.y, g4.y, b4.y);
        hist_px1(myh, r4.z, g4.z, b4.z);
        hist_px1(myh, r4.w, g4.w, b4.w);
    }
    __syncthreads();

    for (int b = tid; b < NUM_BINS; b += blockDim.x) {
        unsigned s = 0;
        #pragma unroll
        for (int w = 0; w < WARPS_PER_BLOCK; w++) s += sh[w][b];
        if (s) atomicAdd(&g_hist1[b], s);
    }
}

// ------------------------------- K3 ----------------------------------------
__global__ __launch_bounds__(NUM_BINS)
void params_kernel() {
    __shared__ float acc[NUM_BINS];
    const int tid = threadIdx.x;

    float maxv = fkey_decode(g_maxbits);
    bool  is_norm = (maxv <= 1.0f);
    float scale = is_norm ? 255.0f : 1.0f;

    float v = (float)(is_norm ? g_hist255[tid] : g_hist1[tid]);

    acc[tid] = v;
    __syncthreads();
    #pragma unroll
    for (int off = 1; off < NUM_BINS; off <<= 1) {
        float add = (tid >= off) ? acc[tid - off] : 0.0f;
        __syncthreads();
        acc[tid] += add;
        __syncthreads();
    }

    float maximum = acc[NUM_BINS - 1];
    float clip = (maximum / 100.0f) / 2.0f;          // CLIP_HIST_PERCENT = 1.0
    float upper = maximum - clip;

    int min_gray = __syncthreads_count(acc[tid] < clip);
    int max_gray = __syncthreads_count(acc[tid] < upper) - 1;

    if (tid == 0) {
        float span  = fmaxf((float)(max_gray - min_gray), 1.0f);
        float alpha = 255.0f / span;
        float beta  = -(float)min_gray * alpha;
        g_alpha_eff = alpha / scale;
        g_beta_eff  = beta  / scale;
        g_hi        = is_norm ? 1.0f : 255.0f;
        g_identity  = (max_gray > min_gray) ? 0 : 1;
        g_maxbits   = 0u;
    }
    g_hist255[tid] = 0u;
    g_hist1[tid]   = 0u;
}

// ------------------------------- K4 ----------------------------------------
// 2 x 256-bit loads + 2 x 256-bit stores per thread (16 floats), streaming.
__global__ __launch_bounds__(256)
void apply_kernel(const float4* __restrict__ in, float4* __restrict__ out,
                  int n8, int n4) {
    int c0 = blockIdx.x * 512 + threadIdx.x;   // 32B-chunk indices
    int c1 = c0 + 256;

    float4 a0, a1, b0, b1;
    bool ok0 = c0 < n8, ok1 = c1 < n8;
    if (ok0) ldg256_cs(&in[2 * c0], a0, a1);
    if (ok1) ldg256_cs(&in[2 * c1], b0, b1);

    int   ident = g_identity;
    float a  = g_alpha_eff;
    float b  = g_beta_eff;
    float hi = g_hi;

    if (!ident) {
        a0.x = fminf(fmaxf(fmaf(a0.x, a, b), 0.0f), hi);
        a0.y = fminf(fmaxf(fmaf(a0.y, a, b), 0.0f), hi);
        a0.z = fminf(fmaxf(fmaf(a0.z, a, b), 0.0f), hi);
        a0.w = fminf(fmaxf(fmaf(a0.w, a, b), 0.0f), hi);
        a1.x = fminf(fmaxf(fmaf(a1.x, a, b), 0.0f), hi);
        a1.y = fminf(fmaxf(fmaf(a1.y, a, b), 0.0f), hi);
        a1.z = fminf(fmaxf(fmaf(a1.z, a, b), 0.0f), hi);
        a1.w = fminf(fmaxf(fmaf(a1.w, a, b), 0.0f), hi);
        b0.x = fminf(fmaxf(fmaf(b0.x, a, b), 0.0f), hi);
        b0.y = fminf(fmaxf(fmaf(b0.y, a, b), 0.0f), hi);
        b0.z = fminf(fmaxf(fmaf(b0.z, a, b), 0.0f), hi);
        b0.w = fminf(fmaxf(fmaf(b0.w, a, b), 0.0f), hi);
        b1.x = fminf(fmaxf(fmaf(b1.x, a, b), 0.0f), hi);
        b1.y = fminf(fmaxf(fmaf(b1.y, a, b), 0.0f), hi);
        b1.z = fminf(fmaxf(fmaf(b1.z, a, b), 0.0f), hi);
        b1.w = fminf(fmaxf(fmaf(b1.w, a, b), 0.0f), hi);
    }
    if (ok0) stg256_cs(&out[2 * c0], a0, a1);
    if (ok1) stg256_cs(&out[2 * c1], b0, b1);

    // odd-tail float4 (only if n4 odd; not hit for this shape)
    if (blockIdx.x == 0 && threadIdx.x == 0 && (2 * n8) < n4) {
        int t = 2 * n8;
        float4 v = in[t];
        if (!ident) {
            v.x = fminf(fmaxf(fmaf(v.x, a, b), 0.0f), hi);
            v.y = fminf(fmaxf(fmaf(v.y, a, b), 0.0f), hi);
            v.z = fminf(fmaxf(fmaf(v.z, a, b), 0.0f), hi);
            v.w = fminf(fmaxf(fmaf(v.w, a, b), 0.0f), hi);
        }
        out[t] = v;
    }
}

// ---------------------------------------------------------------------------
extern "C" void kernel_launch(void* const* d_in, const int* in_sizes, int n_in,
                              void* d_out, int out_size) {
    const float* img = (const float*)d_in[0];
    int n_total = in_sizes[0];
    int n_per   = n_total / 3;
    int n4per   = n_per / 4;
    int n4      = n_total / 4;
    int n8      = n_total / 8;

    hist255_max_kernel<<<HIST_BLOCKS, HIST_THREADS>>>((const float4*)img, n4per);
    hist1_kernel<<<HIST_BLOCKS, HIST_THREADS>>>((const float4*)img, n4per);
    params_kernel<<<1, NUM_BINS>>>();
    int apply_blocks = (n8 + 511) / 512;
    apply_kernel<<<apply_blocks, 256>>>((const float4*)img, (float4*)d_out, n8, n4);
}